// round 15
// baseline (speedup 1.0000x reference)
#include <cuda_runtime.h>
#include <cuda_bf16.h>
#include <cuda_fp16.h>
#include <cstdint>

#define NN      100000
#define EE      1600000
#define INDIM   512
#define HID     64
#define NCLS    16
#define NCH     ((NN + 1023) / 1024)     // 98 scan chunks
#define NBZERO  ((NN + 255) / 256)
#define NBPREP  ((HID * INDIM + 255) / 256)
#define NBGEMM  ((NN + 127) / 128)       // 782 gemm1 tiles
#define NBG1    (NBGEMM / 2)             // 391 tiles in launch A
#define NBG2    (NBGEMM - NBG1)          // 391 tiles in launch B
#define NBHIST  ((EE + 255) / 256)       // 6250 edge blocks
#define NBFILL  ((EE + 255) / 256)

// ---------------- scratch (static device globals; no allocation) -------------
__device__ float g_deg[NN];
__device__ float g_dis[NN];
__device__ float g_selfnorm[NN];
__device__ __half g_h1h[(size_t)NN * HID];
__device__ float g_agg1[(size_t)NN * HID];
__device__ float g_h2[(size_t)NN * NCLS];
__device__ int   g_count[NN];
__device__ int   g_off[NN];
__device__ int   g_cursor[NN];
__device__ int   g_bsum[128];            // chunk totals, +1-encoded ready flag
__device__ int2  g_edge[EE];             // (src, full-norm bits) sorted by dst
__device__ __half g_w1t_hi[HID * INDIM];
__device__ __half g_w1t_lo[HID * INDIM];

// ---------------- helpers -----------------------------------------------------
__device__ __forceinline__ void mma_f16(float& d0, float& d1, float& d2, float& d3,
                                        uint32_t a0, uint32_t a1, uint32_t a2, uint32_t a3,
                                        uint32_t b0, uint32_t b1) {
    asm volatile(
        "mma.sync.aligned.m16n8k16.row.col.f32.f16.f16.f32 "
        "{%0,%1,%2,%3}, {%4,%5,%6,%7}, {%8,%9}, {%0,%1,%2,%3};"
        : "+f"(d0), "+f"(d1), "+f"(d2), "+f"(d3)
        : "r"(a0), "r"(a1), "r"(a2), "r"(a3), "r"(b0), "r"(b1));
}

// ---------------- fused init: zero counters/bsum + W1^T fp16 split ------------
__global__ void k_init(const float* __restrict__ W1) {
    if (blockIdx.x < NBZERO) {
        int i = blockIdx.x * 256 + threadIdx.x;
        if (i < NN) { g_count[i] = 0; g_deg[i] = 1.0f; }
        if (blockIdx.x == 0 && threadIdx.x < 128) g_bsum[threadIdx.x] = 0;
    } else {
        int idx = (blockIdx.x - NBZERO) * 256 + threadIdx.x;
        if (idx < HID * INDIM) {
            int n = idx >> 9;
            int k = idx & 511;
            float w = W1[k * HID + n];
            __half h = __float2half_rn(w);
            g_w1t_hi[n * INDIM + k] = h;
            g_w1t_lo[n * INDIM + k] = __float2half_rn(w - __half2float(h));
        }
    }
}

// ---------------- GEMM1 tile body (shared by both fused launches) -------------
#define KC     32
#define APITCH 40
#define APB    (APITCH * 2)

__device__ __forceinline__ void gemm1_tile(int tile, const float* __restrict__ x) {
    __shared__ uint8_t As   [128 * APB];
    __shared__ uint8_t Bs_hi[64 * APB];
    __shared__ uint8_t Bs_lo[64 * APB];

    int tid = threadIdx.x;
    int wid = tid >> 5;
    int lane = tid & 31;
    int lt = lane >> 2;
    int q  = lane & 3;
    int row0 = tile * 128;

    float acc[8][4];
#pragma unroll
    for (int t = 0; t < 8; t++)
#pragma unroll
        for (int j = 0; j < 4; j++) acc[t][j] = 0.0f;

    const uint2* whi = reinterpret_cast<const uint2*>(g_w1t_hi);
    const uint2* wlo = reinterpret_cast<const uint2*>(g_w1t_lo);

    float4 vx[4];
    uint2  vbh[2], vbl[2];

    auto load_g = [&](int k0) {
#pragma unroll
        for (int i = 0; i < 4; i++) {
            int idx = tid + i * 256;
            int r = idx >> 3;
            int c4 = (idx & 7) * 4;
            int grow = row0 + r;
            vx[i] = (grow < NN)
                ? *reinterpret_cast<const float4*>(&x[(size_t)grow * INDIM + k0 + c4])
                : make_float4(0.f, 0.f, 0.f, 0.f);
        }
#pragma unroll
        for (int i = 0; i < 2; i++) {
            int idx = tid + i * 256;
            int n = idx >> 3;
            int j = idx & 7;
            int gidx = n * 128 + (k0 >> 2) + j;
            vbh[i] = whi[gidx];
            vbl[i] = wlo[gidx];
        }
    };

    auto store_s = [&]() {
#pragma unroll
        for (int i = 0; i < 4; i++) {
            int idx = tid + i * 256;
            int r = idx >> 3;
            int c4 = (idx & 7) * 4;
            float4 v = vx[i];
            __half2 p0 = __floats2half2_rn(v.x, v.y);
            __half2 p1 = __floats2half2_rn(v.z, v.w);
            uint32_t off = (uint32_t)(r * APB + c4 * 2);
            *reinterpret_cast<uint2*>(As + off) =
                make_uint2(*reinterpret_cast<uint32_t*>(&p0),
                           *reinterpret_cast<uint32_t*>(&p1));
        }
#pragma unroll
        for (int i = 0; i < 2; i++) {
            int idx = tid + i * 256;
            int n = idx >> 3;
            int j = idx & 7;
            uint32_t off = (uint32_t)(n * APB + j * 8);
            *reinterpret_cast<uint2*>(Bs_hi + off) = vbh[i];
            *reinterpret_cast<uint2*>(Bs_lo + off) = vbl[i];
        }
    };

    load_g(0);
    store_s();
    __syncthreads();

    for (int c = 0; c < INDIM / KC; c++) {
        bool more = (c + 1 < INDIM / KC);
        if (more) load_g((c + 1) * KC);

#pragma unroll
        for (int ks = 0; ks < 2; ks++) {
            uint32_t abase = (uint32_t)((wid * 16 + lt) * APB + ks * 32 + q * 4);
            uint32_t a0 = *reinterpret_cast<const uint32_t*>(As + abase);
            uint32_t a1 = *reinterpret_cast<const uint32_t*>(As + abase + 8 * APB);
            uint32_t a2 = *reinterpret_cast<const uint32_t*>(As + abase + 16);
            uint32_t a3 = *reinterpret_cast<const uint32_t*>(As + abase + 8 * APB + 16);
#pragma unroll
            for (int nt = 0; nt < 8; nt++) {
                uint32_t bbase = (uint32_t)((nt * 8 + lt) * APB + ks * 32 + q * 4);
                uint32_t bh0 = *reinterpret_cast<const uint32_t*>(Bs_hi + bbase);
                uint32_t bh1 = *reinterpret_cast<const uint32_t*>(Bs_hi + bbase + 16);
                uint32_t bl0 = *reinterpret_cast<const uint32_t*>(Bs_lo + bbase);
                uint32_t bl1 = *reinterpret_cast<const uint32_t*>(Bs_lo + bbase + 16);
                mma_f16(acc[nt][0], acc[nt][1], acc[nt][2], acc[nt][3],
                        a0, a1, a2, a3, bh0, bh1);
                mma_f16(acc[nt][0], acc[nt][1], acc[nt][2], acc[nt][3],
                        a0, a1, a2, a3, bl0, bl1);
            }
        }
        __syncthreads();
        if (more) {
            store_s();
            __syncthreads();
        }
    }

    int rA = row0 + wid * 16 + lt;
    int rB = rA + 8;
#pragma unroll
    for (int nt = 0; nt < 8; nt++) {
        int col = nt * 8 + q * 2;
        if (rA < NN)
            *reinterpret_cast<__half2*>(&g_h1h[(size_t)rA * HID + col]) =
                __floats2half2_rn(acc[nt][0], acc[nt][1]);
        if (rB < NN)
            *reinterpret_cast<__half2*>(&g_h1h[(size_t)rB * HID + col]) =
                __floats2half2_rn(acc[nt][2], acc[nt][3]);
    }
}

// ---------------- launch A: gemm tiles [0,NBG1) + histogram -------------------
__global__ void __launch_bounds__(256)
k_gemm_hist(const float* __restrict__ x,
            const int* __restrict__ dst, const float* __restrict__ ew) {
    if (blockIdx.x < NBG1) {
        gemm1_tile(blockIdx.x, x);
        return;
    }
    int e = (blockIdx.x - NBG1) * 256 + threadIdx.x;
    if (e < EE) {
        int d = dst[e];
        atomicAdd(&g_count[d], 1);
        atomicAdd(&g_deg[d], ew[e]);
    }
}

// ---------------- single-kernel scan (publish totals + parallel carry sum) ----
__global__ void __launch_bounds__(1024)
k_scan() {
    __shared__ int sm[1024];
    __shared__ int carry_s;
    int tid = threadIdx.x;
    int b = blockIdx.x;
    int i = b * 1024 + tid;
    int v = (i < NN) ? g_count[i] : 0;
    sm[tid] = v;
    __syncthreads();
#pragma unroll
    for (int off = 1; off < 1024; off <<= 1) {
        int t = (tid >= off) ? sm[tid - off] : 0;
        __syncthreads();
        sm[tid] += t;
        __syncthreads();
    }
    int incl = sm[tid];
    if (tid == 1023) atomicExch(&g_bsum[b], incl + 1);   // publish chunk total
    if (tid < 32) {                                       // sum predecessor totals
        int part = 0;
        for (int k = tid; k < b; k += 32) {
            int val;
            do { val = atomicAdd(&g_bsum[k], 0); } while (val == 0);
            part += val - 1;
        }
#pragma unroll
        for (int m = 16; m; m >>= 1) part += __shfl_xor_sync(0xFFFFFFFFu, part, m);
        if (tid == 0) carry_s = part;
    }
    __syncthreads();
    if (i < NN) {
        int o = incl - v + carry_s;
        g_off[i] = o;
        g_cursor[i] = o;
        float r = rsqrtf(g_deg[i]);
        g_dis[i] = r;
        g_selfnorm[i] = r * r;
    }
}

// ---------------- launch B: gemm tiles [NBG1,NBGEMM) + fill -------------------
__global__ void __launch_bounds__(256)
k_gemm_fill(const float* __restrict__ x,
            const int* __restrict__ src, const int* __restrict__ dst,
            const float* __restrict__ ew) {
    if (blockIdx.x < NBG2) {
        gemm1_tile(NBG1 + blockIdx.x, x);
        return;
    }
    int e = (blockIdx.x - NBG2) * 256 + threadIdx.x;
    if (e >= EE) return;
    int s = src[e], d = dst[e];
    int pos = atomicAdd(&g_cursor[d], 1);
    float nm = g_dis[s] * ew[e] * g_dis[d];
    g_edge[pos] = make_int2(s, __float_as_int(nm));
}

// ---------------- layer-1 aggregation: warp per dst, 8-edge unrolled ----------
__global__ void __launch_bounds__(256)
k_agg1() {
    int d = blockIdx.x * 8 + (threadIdx.x >> 5);
    if (d >= NN) return;
    int lane = threadIdx.x & 31;
    int start = g_off[d], n = g_count[d];
    float sl = g_selfnorm[d];
    __half2 hv = *reinterpret_cast<const __half2*>(&g_h1h[(size_t)d * HID + lane * 2]);
    float2 v0 = __half22float2(hv);
    float2 acc = make_float2(v0.x * sl, v0.y * sl);
    const int2* ep = g_edge + start;
    int j = 0;
    for (; j + 8 <= n; j += 8) {
        int2 e[8];
        __half2 h[8];
#pragma unroll
        for (int u = 0; u < 8; u++) e[u] = ep[j + u];
#pragma unroll
        for (int u = 0; u < 8; u++)
            h[u] = *reinterpret_cast<const __half2*>(&g_h1h[(size_t)e[u].x * HID + lane * 2]);
#pragma unroll
        for (int u = 0; u < 8; u++) {
            float nm = __int_as_float(e[u].y);
            float2 f = __half22float2(h[u]);
            acc.x = fmaf(f.x, nm, acc.x);
            acc.y = fmaf(f.y, nm, acc.y);
        }
    }
    for (; j < n; j++) {
        int2 ed = ep[j];
        float nm = __int_as_float(ed.y);
        __half2 h = *reinterpret_cast<const __half2*>(&g_h1h[(size_t)ed.x * HID + lane * 2]);
        float2 v = __half22float2(h);
        acc.x = fmaf(v.x, nm, acc.x);
        acc.y = fmaf(v.y, nm, acc.y);
    }
    *reinterpret_cast<float2*>(&g_agg1[(size_t)d * HID + lane * 2]) = acc;
}

// ---------------- GEMM2: relu(agg1+b1) @ W2 -> h2 ----------------------------
__global__ void k_gemm2(const float* __restrict__ b1, const float* __restrict__ W2) {
    __shared__ float w2s[HID * NCLS];
    __shared__ float b1s[HID];
    int tid = threadIdx.x;
    for (int i = tid; i < HID * NCLS; i += blockDim.x) w2s[i] = W2[i];
    if (tid < HID) b1s[tid] = b1[tid];
    __syncthreads();
    int row = blockIdx.x * blockDim.x + tid;
    if (row >= NN) return;
    float acc[NCLS];
#pragma unroll
    for (int c = 0; c < NCLS; c++) acc[c] = 0.0f;
    const float4* arow = reinterpret_cast<const float4*>(&g_agg1[(size_t)row * HID]);
#pragma unroll
    for (int k4 = 0; k4 < HID / 4; k4++) {
        float4 v = arow[k4];
        float z0 = fmaxf(v.x + b1s[4 * k4 + 0], 0.0f);
        float z1 = fmaxf(v.y + b1s[4 * k4 + 1], 0.0f);
        float z2 = fmaxf(v.z + b1s[4 * k4 + 2], 0.0f);
        float z3 = fmaxf(v.w + b1s[4 * k4 + 3], 0.0f);
#pragma unroll
        for (int c = 0; c < NCLS; c++) {
            acc[c] = fmaf(z0, w2s[(4 * k4 + 0) * NCLS + c], acc[c]);
            acc[c] = fmaf(z1, w2s[(4 * k4 + 1) * NCLS + c], acc[c]);
            acc[c] = fmaf(z2, w2s[(4 * k4 + 2) * NCLS + c], acc[c]);
            acc[c] = fmaf(z3, w2s[(4 * k4 + 3) * NCLS + c], acc[c]);
        }
    }
#pragma unroll
    for (int c = 0; c < NCLS; c++) g_h2[(size_t)row * NCLS + c] = acc[c];
}

// ---------------- layer-2 aggregation + bias + log_softmax (fused) ------------
__global__ void __launch_bounds__(256)
k_agg2_sm(const float* __restrict__ b2, float* __restrict__ out) {
    int warp = blockIdx.x * 8 + (threadIdx.x >> 5);
    int lane = threadIdx.x & 31;
    int d = warp * 2 + (lane >> 4);
    int f = lane & 15;
    if (d >= NN) return;
    int start = g_off[d], n = g_count[d];
    float acc = g_h2[(size_t)d * NCLS + f] * g_selfnorm[d];
    const int2* ep = g_edge + start;
    int j = 0;
    for (; j + 4 <= n; j += 4) {
        int2 e0 = ep[j], e1 = ep[j + 1], e2 = ep[j + 2], e3 = ep[j + 3];
        float v0 = g_h2[(size_t)e0.x * NCLS + f];
        float v1 = g_h2[(size_t)e1.x * NCLS + f];
        float v2 = g_h2[(size_t)e2.x * NCLS + f];
        float v3 = g_h2[(size_t)e3.x * NCLS + f];
        acc = fmaf(v0, __int_as_float(e0.y), acc);
        acc = fmaf(v1, __int_as_float(e1.y), acc);
        acc = fmaf(v2, __int_as_float(e2.y), acc);
        acc = fmaf(v3, __int_as_float(e3.y), acc);
    }
    for (; j < n; j++) {
        int2 ed = ep[j];
        acc = fmaf(g_h2[(size_t)ed.x * NCLS + f], __int_as_float(ed.y), acc);
    }
    float v = acc + b2[f];
    float m = v;
#pragma unroll
    for (int msk = 8; msk; msk >>= 1) m = fmaxf(m, __shfl_xor_sync(0xFFFFFFFFu, m, msk));
    float s = expf(v - m);
#pragma unroll
    for (int msk = 8; msk; msk >>= 1) s += __shfl_xor_sync(0xFFFFFFFFu, s, msk);
    out[(size_t)d * NCLS + f] = v - (logf(s) + m);
}

// ---------------- launch ------------------------------------------------------
extern "C" void kernel_launch(void* const* d_in, const int* in_sizes, int n_in,
                              void* d_out, int out_size) {
    const float* x  = (const float*)d_in[0];
    const int*   ei = (const int*)  d_in[1];
    const float* ew = (const float*)d_in[2];
    const float* W1 = (const float*)d_in[3];
    const float* b1 = (const float*)d_in[4];
    const float* W2 = (const float*)d_in[5];
    const float* b2 = (const float*)d_in[6];
    float* out = (float*)d_out;

    const int* src = ei;
    const int* dst = ei + EE;

    k_init      <<<NBZERO + NBPREP, 256>>>(W1);
    k_gemm_hist <<<NBG1 + NBHIST, 256>>>(x, dst, ew);        // gemm A ∥ hist
    k_scan      <<<NCH, 1024>>>();                           // fused 3-in-1 scan
    k_gemm_fill <<<NBG2 + NBFILL, 256>>>(x, src, dst, ew);   // gemm B ∥ fill
    k_agg1      <<<(NN + 7) / 8, 256>>>();
    k_gemm2     <<<(NN + 255) / 256, 256>>>(b1, W2);
    k_agg2_sm   <<<(NN / 2 + 7) / 8, 256>>>(b2, out);
}

// round 17
// speedup vs baseline: 1.0446x; 1.0446x over previous
#include <cuda_runtime.h>
#include <cuda_bf16.h>
#include <cuda_fp16.h>
#include <cstdint>

#define NN      100000
#define EE      1600000
#define INDIM   512
#define HID     64
#define NCLS    16
#define NCH     ((NN + 1023) / 1024)     // 98 scan chunks
#define NBZERO  ((NN + 255) / 256)
#define NBPREP  ((HID * INDIM + 255) / 256)
#define NBGEMM  ((NN + 127) / 128)       // 782 gemm1 tiles
#define NBHIST  ((EE + 255) / 256)       // 6250 edge blocks

// ---------------- scratch (static device globals; no allocation) -------------
__device__ float g_deg[NN];
__device__ float g_dis[NN];
__device__ float g_selfnorm[NN];
__device__ __half g_h1h[(size_t)NN * HID];
__device__ float g_h2[(size_t)NN * NCLS];
__device__ int   g_count[NN];
__device__ int   g_off[NN];
__device__ int   g_cursor[NN];
__device__ int   g_bsum[128];            // chunk totals, +1-encoded ready flag
__device__ int2  g_edge[EE];             // (src, full-norm bits) sorted by dst
__device__ __half g_w1t_hi[HID * INDIM];
__device__ __half g_w1t_lo[HID * INDIM];

// ---------------- helpers -----------------------------------------------------
__device__ __forceinline__ void mma_f16(float& d0, float& d1, float& d2, float& d3,
                                        uint32_t a0, uint32_t a1, uint32_t a2, uint32_t a3,
                                        uint32_t b0, uint32_t b1) {
    asm volatile(
        "mma.sync.aligned.m16n8k16.row.col.f32.f16.f16.f32 "
        "{%0,%1,%2,%3}, {%4,%5,%6,%7}, {%8,%9}, {%0,%1,%2,%3};"
        : "+f"(d0), "+f"(d1), "+f"(d2), "+f"(d3)
        : "r"(a0), "r"(a1), "r"(a2), "r"(a3), "r"(b0), "r"(b1));
}

// ---------------- fused init: zero counters/bsum + W1^T fp16 split ------------
__global__ void k_init(const float* __restrict__ W1) {
    if (blockIdx.x < NBZERO) {
        int i = blockIdx.x * 256 + threadIdx.x;
        if (i < NN) { g_count[i] = 0; g_deg[i] = 1.0f; }
        if (blockIdx.x == 0 && threadIdx.x < 128) g_bsum[threadIdx.x] = 0;
    } else {
        int idx = (blockIdx.x - NBZERO) * 256 + threadIdx.x;
        if (idx < HID * INDIM) {
            int n = idx >> 9;
            int k = idx & 511;
            float w = W1[k * HID + n];
            __half h = __float2half_rn(w);
            g_w1t_hi[n * INDIM + k] = h;
            g_w1t_lo[n * INDIM + k] = __float2half_rn(w - __half2float(h));
        }
    }
}

// ---------------- FUSED: full GEMM1 (blocks [0,NBGEMM)) + hist ----------------
#define KC     32
#define APITCH 40
#define APB    (APITCH * 2)

__global__ void __launch_bounds__(256)
k_gemm_hist(const float* __restrict__ x,
            const int* __restrict__ dst, const float* __restrict__ ew) {
    __shared__ uint8_t As   [128 * APB];
    __shared__ uint8_t Bs_hi[64 * APB];
    __shared__ uint8_t Bs_lo[64 * APB];

    if (blockIdx.x >= NBGEMM) {
        int e = (blockIdx.x - NBGEMM) * 256 + threadIdx.x;
        if (e < EE) {
            int d = dst[e];
            atomicAdd(&g_count[d], 1);
            atomicAdd(&g_deg[d], ew[e]);
        }
        return;
    }

    int tid = threadIdx.x;
    int wid = tid >> 5;
    int lane = tid & 31;
    int lt = lane >> 2;
    int q  = lane & 3;
    int row0 = blockIdx.x * 128;

    float acc[8][4];
#pragma unroll
    for (int t = 0; t < 8; t++)
#pragma unroll
        for (int j = 0; j < 4; j++) acc[t][j] = 0.0f;

    const uint2* whi = reinterpret_cast<const uint2*>(g_w1t_hi);
    const uint2* wlo = reinterpret_cast<const uint2*>(g_w1t_lo);

    float4 vx[4];
    uint2  vbh[2], vbl[2];

    auto load_g = [&](int k0) {
#pragma unroll
        for (int i = 0; i < 4; i++) {
            int idx = tid + i * 256;
            int r = idx >> 3;
            int c4 = (idx & 7) * 4;
            int grow = row0 + r;
            vx[i] = (grow < NN)
                ? *reinterpret_cast<const float4*>(&x[(size_t)grow * INDIM + k0 + c4])
                : make_float4(0.f, 0.f, 0.f, 0.f);
        }
#pragma unroll
        for (int i = 0; i < 2; i++) {
            int idx = tid + i * 256;
            int n = idx >> 3;
            int j = idx & 7;
            int gidx = n * 128 + (k0 >> 2) + j;
            vbh[i] = whi[gidx];
            vbl[i] = wlo[gidx];
        }
    };

    auto store_s = [&]() {
#pragma unroll
        for (int i = 0; i < 4; i++) {
            int idx = tid + i * 256;
            int r = idx >> 3;
            int c4 = (idx & 7) * 4;
            float4 v = vx[i];
            __half2 p0 = __floats2half2_rn(v.x, v.y);
            __half2 p1 = __floats2half2_rn(v.z, v.w);
            uint32_t off = (uint32_t)(r * APB + c4 * 2);
            *reinterpret_cast<uint2*>(As + off) =
                make_uint2(*reinterpret_cast<uint32_t*>(&p0),
                           *reinterpret_cast<uint32_t*>(&p1));
        }
#pragma unroll
        for (int i = 0; i < 2; i++) {
            int idx = tid + i * 256;
            int n = idx >> 3;
            int j = idx & 7;
            uint32_t off = (uint32_t)(n * APB + j * 8);
            *reinterpret_cast<uint2*>(Bs_hi + off) = vbh[i];
            *reinterpret_cast<uint2*>(Bs_lo + off) = vbl[i];
        }
    };

    load_g(0);
    store_s();
    __syncthreads();

    for (int c = 0; c < INDIM / KC; c++) {
        bool more = (c + 1 < INDIM / KC);
        if (more) load_g((c + 1) * KC);

#pragma unroll
        for (int ks = 0; ks < 2; ks++) {
            uint32_t abase = (uint32_t)((wid * 16 + lt) * APB + ks * 32 + q * 4);
            uint32_t a0 = *reinterpret_cast<const uint32_t*>(As + abase);
            uint32_t a1 = *reinterpret_cast<const uint32_t*>(As + abase + 8 * APB);
            uint32_t a2 = *reinterpret_cast<const uint32_t*>(As + abase + 16);
            uint32_t a3 = *reinterpret_cast<const uint32_t*>(As + abase + 8 * APB + 16);
#pragma unroll
            for (int nt = 0; nt < 8; nt++) {
                uint32_t bbase = (uint32_t)((nt * 8 + lt) * APB + ks * 32 + q * 4);
                uint32_t bh0 = *reinterpret_cast<const uint32_t*>(Bs_hi + bbase);
                uint32_t bh1 = *reinterpret_cast<const uint32_t*>(Bs_hi + bbase + 16);
                uint32_t bl0 = *reinterpret_cast<const uint32_t*>(Bs_lo + bbase);
                uint32_t bl1 = *reinterpret_cast<const uint32_t*>(Bs_lo + bbase + 16);
                mma_f16(acc[nt][0], acc[nt][1], acc[nt][2], acc[nt][3],
                        a0, a1, a2, a3, bh0, bh1);
                mma_f16(acc[nt][0], acc[nt][1], acc[nt][2], acc[nt][3],
                        a0, a1, a2, a3, bl0, bl1);
            }
        }
        __syncthreads();
        if (more) {
            store_s();
            __syncthreads();
        }
    }

    int rA = row0 + wid * 16 + lt;
    int rB = rA + 8;
#pragma unroll
    for (int nt = 0; nt < 8; nt++) {
        int col = nt * 8 + q * 2;
        if (rA < NN)
            *reinterpret_cast<__half2*>(&g_h1h[(size_t)rA * HID + col]) =
                __floats2half2_rn(acc[nt][0], acc[nt][1]);
        if (rB < NN)
            *reinterpret_cast<__half2*>(&g_h1h[(size_t)rB * HID + col]) =
                __floats2half2_rn(acc[nt][2], acc[nt][3]);
    }
}

// ---------------- single-kernel scan (publish totals + parallel carry sum) ----
__global__ void __launch_bounds__(1024)
k_scan() {
    __shared__ int sm[1024];
    __shared__ int carry_s;
    int tid = threadIdx.x;
    int b = blockIdx.x;
    int i = b * 1024 + tid;
    int v = (i < NN) ? g_count[i] : 0;
    sm[tid] = v;
    __syncthreads();
#pragma unroll
    for (int off = 1; off < 1024; off <<= 1) {
        int t = (tid >= off) ? sm[tid - off] : 0;
        __syncthreads();
        sm[tid] += t;
        __syncthreads();
    }
    int incl = sm[tid];
    if (tid == 1023) atomicExch(&g_bsum[b], incl + 1);   // publish chunk total
    if (tid < 32) {                                       // sum predecessor totals
        int part = 0;
        for (int k = tid; k < b; k += 32) {
            int val;
            do { val = atomicAdd(&g_bsum[k], 0); } while (val == 0);
            part += val - 1;
        }
#pragma unroll
        for (int m = 16; m; m >>= 1) part += __shfl_xor_sync(0xFFFFFFFFu, part, m);
        if (tid == 0) carry_s = part;
    }
    __syncthreads();
    if (i < NN) {
        int o = incl - v + carry_s;
        g_off[i] = o;
        g_cursor[i] = o;
        float r = rsqrtf(g_deg[i]);
        g_dis[i] = r;
        g_selfnorm[i] = r * r;
    }
}

// fill with FULL norm dis[src]*w*dis[dst]
__global__ void k_fill(const int* __restrict__ src, const int* __restrict__ dst,
                       const float* __restrict__ ew) {
    int e = blockIdx.x * blockDim.x + threadIdx.x;
    if (e >= EE) return;
    int s = src[e], d = dst[e];
    int pos = atomicAdd(&g_cursor[d], 1);
    float nm = g_dis[s] * ew[e] * g_dis[d];
    g_edge[pos] = make_int2(s, __float_as_int(nm));
}

// ---------------- FUSED: layer-1 aggregate + relu + GEMM2 -> h2 ---------------
// Phase 1: warp per dst, 8-edge unrolled gather; relu(acc+b1) -> zs (smem).
// Phase 2: threads 0..127 each compute one (row, class) via uniform 64-FMA loop.
// All indexing static or bank-friendly; NO dynamic register-array access.
__global__ void __launch_bounds__(256)
k_agg1g2(const float* __restrict__ b1, const float* __restrict__ W2) {
    __shared__ float w2s[HID * NCLS];
    __shared__ float b1s[HID];
    __shared__ float zs[8][HID];
    int tid = threadIdx.x;
    for (int i = tid; i < HID * NCLS; i += 256) w2s[i] = W2[i];
    if (tid < HID) b1s[tid] = b1[tid];
    __syncthreads();

    int wrp = tid >> 5;
    int lane = tid & 31;
    int d = blockIdx.x * 8 + wrp;        // NN == 12500*8, never out of range
    int start = g_off[d], n = g_count[d];
    float sl = g_selfnorm[d];
    __half2 hv = *reinterpret_cast<const __half2*>(&g_h1h[(size_t)d * HID + lane * 2]);
    float2 v0 = __half22float2(hv);
    float2 acc = make_float2(v0.x * sl, v0.y * sl);
    const int2* ep = g_edge + start;
    int j = 0;
    for (; j + 8 <= n; j += 8) {
        int2 e[8];
        __half2 h[8];
#pragma unroll
        for (int u = 0; u < 8; u++) e[u] = ep[j + u];
#pragma unroll
        for (int u = 0; u < 8; u++)
            h[u] = *reinterpret_cast<const __half2*>(&g_h1h[(size_t)e[u].x * HID + lane * 2]);
#pragma unroll
        for (int u = 0; u < 8; u++) {
            float nm = __int_as_float(e[u].y);
            float2 f = __half22float2(h[u]);
            acc.x = fmaf(f.x, nm, acc.x);
            acc.y = fmaf(f.y, nm, acc.y);
        }
    }
    for (; j < n; j++) {
        int2 ed = ep[j];
        float nm = __int_as_float(ed.y);
        __half2 h = *reinterpret_cast<const __half2*>(&g_h1h[(size_t)ed.x * HID + lane * 2]);
        float2 v = __half22float2(h);
        acc.x = fmaf(v.x, nm, acc.x);
        acc.y = fmaf(v.y, nm, acc.y);
    }
    // relu + bias into smem handoff (static/vector indices only)
    zs[wrp][2 * lane]     = fmaxf(acc.x + b1s[2 * lane], 0.0f);
    zs[wrp][2 * lane + 1] = fmaxf(acc.y + b1s[2 * lane + 1], 0.0f);
    __syncthreads();

    if (tid < 128) {
        int row = tid >> 4;
        int c = tid & 15;
        int dd = blockIdx.x * 8 + row;
        float s = 0.0f;
#pragma unroll
        for (int k = 0; k < HID; k++)
            s = fmaf(zs[row][k], w2s[k * NCLS + c], s);
        g_h2[(size_t)dd * NCLS + c] = s;
    }
}

// ---------------- layer-2 aggregation + bias + log_softmax (fused) ------------
__global__ void __launch_bounds__(256)
k_agg2_sm(const float* __restrict__ b2, float* __restrict__ out) {
    int warp = blockIdx.x * 8 + (threadIdx.x >> 5);
    int lane = threadIdx.x & 31;
    int d = warp * 2 + (lane >> 4);
    int f = lane & 15;
    if (d >= NN) return;
    int start = g_off[d], n = g_count[d];
    float acc = g_h2[(size_t)d * NCLS + f] * g_selfnorm[d];
    const int2* ep = g_edge + start;
    int j = 0;
    for (; j + 4 <= n; j += 4) {
        int2 e0 = ep[j], e1 = ep[j + 1], e2 = ep[j + 2], e3 = ep[j + 3];
        float v0 = g_h2[(size_t)e0.x * NCLS + f];
        float v1 = g_h2[(size_t)e1.x * NCLS + f];
        float v2 = g_h2[(size_t)e2.x * NCLS + f];
        float v3 = g_h2[(size_t)e3.x * NCLS + f];
        acc = fmaf(v0, __int_as_float(e0.y), acc);
        acc = fmaf(v1, __int_as_float(e1.y), acc);
        acc = fmaf(v2, __int_as_float(e2.y), acc);
        acc = fmaf(v3, __int_as_float(e3.y), acc);
    }
    for (; j < n; j++) {
        int2 ed = ep[j];
        acc = fmaf(g_h2[(size_t)ed.x * NCLS + f], __int_as_float(ed.y), acc);
    }
    float v = acc + b2[f];
    float m = v;
#pragma unroll
    for (int msk = 8; msk; msk >>= 1) m = fmaxf(m, __shfl_xor_sync(0xFFFFFFFFu, m, msk));
    float s = expf(v - m);
#pragma unroll
    for (int msk = 8; msk; msk >>= 1) s += __shfl_xor_sync(0xFFFFFFFFu, s, msk);
    out[(size_t)d * NCLS + f] = v - (logf(s) + m);
}

// ---------------- launch ------------------------------------------------------
extern "C" void kernel_launch(void* const* d_in, const int* in_sizes, int n_in,
                              void* d_out, int out_size) {
    const float* x  = (const float*)d_in[0];
    const int*   ei = (const int*)  d_in[1];
    const float* ew = (const float*)d_in[2];
    const float* W1 = (const float*)d_in[3];
    const float* b1 = (const float*)d_in[4];
    const float* W2 = (const float*)d_in[5];
    const float* b2 = (const float*)d_in[6];
    float* out = (float*)d_out;

    const int* src = ei;
    const int* dst = ei + EE;

    k_init      <<<NBZERO + NBPREP, 256>>>(W1);
    k_gemm_hist <<<NBGEMM + NBHIST, 256>>>(x, dst, ew);    // full gemm ∥ hist
    k_scan      <<<NCH, 1024>>>();                         // fused 3-in-1 scan
    k_fill      <<<(EE + 255) / 256, 256>>>(src, dst, ew);
    k_agg1g2    <<<NN / 8, 256>>>(b1, W2);                 // agg1 + gemm2 fused
    k_agg2_sm   <<<(NN / 2 + 7) / 8, 256>>>(b2, out);
}